// round 3
// baseline (speedup 1.0000x reference)
#include <cuda_runtime.h>
#include <cuda_fp16.h>
#include <cstdint>

// ---------------------------------------------------------------------------
// Problem constants
// ---------------------------------------------------------------------------
#define B_   32
#define T_   2048
#define D_   1024
#define A_   1024
#define M_ROWS (B_ * T_)          // 65536

// scores GEMM tiling (HMMA mma.sync path — tcgen05 PTX not allowed at compute_103)
#define BM 128
#define BN 128
#define BK 32
#define N_CHUNKS (A_ / BN)        // 8
#define K_TILES  (D_ / BK)        // 32
#define SPAD 40                   // smem row stride in halves (80B, conflict-free for ldsm)

// ---------------------------------------------------------------------------
// Device scratch (static __device__ arrays: the sanctioned no-alloc path)
// ---------------------------------------------------------------------------
__device__ __align__(16) __half g_h16[(size_t)M_ROWS * D_];   // 128 MB
__device__ __align__(16) __half g_U16t[(size_t)A_ * D_];      // U transposed: [a][d]
__device__ __align__(16) float  g_Ws[B_ * A_];
__device__ __align__(16) float  g_scores[B_ * T_];
__device__ __align__(16) float  g_probs[B_ * T_];
__device__ __align__(16) float  g_partial[B_ * 8 * D_];

// ---------------------------------------------------------------------------
// PTX helpers (portable: sm_80-era instructions only)
// ---------------------------------------------------------------------------
__device__ __forceinline__ uint32_t smem_u32(const void* p) {
    uint32_t a;
    asm("{ .reg .u64 t; cvta.to.shared.u64 t, %1; cvt.u32.u64 %0, t; }"
        : "=r"(a) : "l"(p));
    return a;
}

#define CP_ASYNC16(dst, src) \
    asm volatile("cp.async.cg.shared.global [%0], [%1], 16;" :: "r"(dst), "l"(src))
#define CP_COMMIT() asm volatile("cp.async.commit_group;" ::: "memory")
#define CP_WAIT1()  asm volatile("cp.async.wait_group 1;" ::: "memory")
#define CP_WAIT0()  asm volatile("cp.async.wait_group 0;" ::: "memory")

#define LDSM_X4(r0, r1, r2, r3, addr)                                          \
    asm volatile("ldmatrix.sync.aligned.m8n8.x4.shared.b16 {%0,%1,%2,%3}, [%4];" \
                 : "=r"(r0), "=r"(r1), "=r"(r2), "=r"(r3) : "r"(addr))

#define MMA16816(d, a, b0, b1)                                                 \
    asm volatile("mma.sync.aligned.m16n8k16.row.col.f32.f16.f16.f32 "          \
                 "{%0,%1,%2,%3}, {%4,%5,%6,%7}, {%8,%9}, {%0,%1,%2,%3};"       \
                 : "+f"((d)[0]), "+f"((d)[1]), "+f"((d)[2]), "+f"((d)[3])      \
                 : "r"((a)[0]), "r"((a)[1]), "r"((a)[2]), "r"((a)[3]),         \
                   "r"(b0), "r"(b1))

__device__ __forceinline__ float fast_tanh(float x) {
    x = fminf(15.0f, fmaxf(-15.0f, x));
    float e = __expf(2.0f * x);
    return __fdividef(e - 1.0f, e + 1.0f);
}

// ---------------------------------------------------------------------------
// Kernel 1: convert h fp32 -> fp16 (one float4 per thread)
// ---------------------------------------------------------------------------
__global__ void convert_h_kernel(const float* __restrict__ h) {
    size_t i = (size_t)blockIdx.x * 256 + threadIdx.x;   // float4 index
    float4 v = __ldg(((const float4*)h) + i);
    __half2 lo = __floats2half2_rn(v.x, v.y);
    __half2 hi = __floats2half2_rn(v.z, v.w);
    uint2 out;
    out.x = *(uint32_t*)&lo;
    out.y = *(uint32_t*)&hi;
    ((uint2*)g_h16)[i] = out;
}

// ---------------------------------------------------------------------------
// Kernel 2: transpose + convert U_a [d][a] fp32 -> g_U16t [a][d] fp16
// ---------------------------------------------------------------------------
__global__ void transpose_U_kernel(const float* __restrict__ U) {
    __shared__ float tile[32][33];
    int bx = blockIdx.x;  // a tile
    int by = blockIdx.y;  // d tile
    int tx = threadIdx.x, ty = threadIdx.y;
#pragma unroll
    for (int j = 0; j < 4; j++)
        tile[ty + j * 8][tx] = __ldg(&U[(size_t)(by * 32 + ty + j * 8) * A_ + bx * 32 + tx]);
    __syncthreads();
#pragma unroll
    for (int j = 0; j < 4; j++)
        g_U16t[(size_t)(bx * 32 + ty + j * 8) * D_ + by * 32 + tx] =
            __float2half_rn(tile[tx][ty + j * 8]);
}

// ---------------------------------------------------------------------------
// Kernel 3: Ws[b][a] = sum_d s[b][d] * W_a[d][a]   (fp32, small)
// ---------------------------------------------------------------------------
__global__ void ws_kernel(const float* __restrict__ s, const float* __restrict__ W) {
    __shared__ float ss[D_];
    int b = blockIdx.y;
    int a = blockIdx.x * 128 + threadIdx.x;
    for (int i = threadIdx.x; i < D_; i += 128)
        ss[i] = __ldg(&s[b * D_ + i]);
    __syncthreads();
    float acc = 0.0f;
#pragma unroll 8
    for (int d = 0; d < D_; d++)
        acc = fmaf(ss[d], __ldg(&W[(size_t)d * A_ + a]), acc);
    g_Ws[b * A_ + a] = acc;
}

// ---------------------------------------------------------------------------
// Kernel 4: fused scores GEMM (HMMA) + tanh + v_a reduction
//   scores[b,t] = sum_a tanh(Ws[b,a] + sum_d h[b,t,d]*U[d,a]) * v_a[a]
// Block: 128 t-rows. Loops over 8 n-chunks of 128 a-cols; per chunk a
// K=1024 HMMA GEMM with cp.async double buffering; epilogue folds
// tanh(.)·v_a into persistent per-thread row accumulators.
// ---------------------------------------------------------------------------
__global__ void __launch_bounds__(256, 2)
scores_kernel(const float* __restrict__ v_a) {
    __shared__ __half sA[2][BM * SPAD];
    __shared__ __half sB[2][BN * SPAD];
    __shared__ float ws_s[BN];
    __shared__ float v_s[BN];
    __shared__ float s_part[2][BM];

    const int tid = threadIdx.x;
    const int wid = tid >> 5;
    const int lane = tid & 31;
    const int wm = wid & 3;      // 4 warps over M
    const int wn = wid >> 2;     // 2 warps over N
    const int g = lane >> 2;     // group-of-4 id = row within atom
    const int q = lane & 3;      // col pair selector

    const int row0 = blockIdx.x * BM;
    const int b = row0 >> 11;            // T_ = 2048
    const int t0 = row0 & (T_ - 1);

    // ldmatrix lane address selectors (same pattern for A and B)
    const int rsel = lane & 15;
    const int ksel = (lane >> 4) << 3;

    const __half* hbase = g_h16 + (size_t)row0 * D_;

    float rowacc[4] = {0.f, 0.f, 0.f, 0.f};

    for (int nc = 0; nc < N_CHUNKS; nc++) {
        const int n0 = nc * BN;
        __syncthreads();               // prior epilogue done before restaging
        if (tid < BN) {
            ws_s[tid] = g_Ws[b * A_ + n0 + tid];
            v_s[tid]  = __ldg(&v_a[n0 + tid]);
        }

        float acc[2][8][4];
#pragma unroll
        for (int am = 0; am < 2; am++)
#pragma unroll
            for (int j = 0; j < 8; j++)
#pragma unroll
                for (int c = 0; c < 4; c++) acc[am][j][c] = 0.f;

        const __half* ubase = g_U16t + (size_t)n0 * D_;

        // ---- prologue: stage k-tile 0 into buf 0 ----
        {
#pragma unroll
            for (int i = 0; i < 4; i++) {
                int idx = tid + i * 256;           // 0..1023
                int half_sel = idx >> 9;           // 0: A, 1: B
                int r = (idx & 511) >> 2;
                int c = idx & 3;
                const __half* src = half_sel
                    ? (ubase + (size_t)r * D_ + c * 8)
                    : (hbase + (size_t)r * D_ + c * 8);
                uint32_t dst = smem_u32(half_sel ? &sB[0][r * SPAD + c * 8]
                                                 : &sA[0][r * SPAD + c * 8]);
                CP_ASYNC16(dst, src);
            }
            CP_COMMIT();
        }

        int buf = 0;
        for (int kt = 0; kt < K_TILES; kt++) {
            if (kt + 1 < K_TILES) {
                const int k0 = (kt + 1) * BK;
#pragma unroll
                for (int i = 0; i < 4; i++) {
                    int idx = tid + i * 256;
                    int half_sel = idx >> 9;
                    int r = (idx & 511) >> 2;
                    int c = idx & 3;
                    const __half* src = half_sel
                        ? (ubase + (size_t)r * D_ + k0 + c * 8)
                        : (hbase + (size_t)r * D_ + k0 + c * 8);
                    uint32_t dst = smem_u32(half_sel ? &sB[buf ^ 1][r * SPAD + c * 8]
                                                     : &sA[buf ^ 1][r * SPAD + c * 8]);
                    CP_ASYNC16(dst, src);
                }
                CP_COMMIT();
                CP_WAIT1();
            } else {
                CP_WAIT0();
            }
            __syncthreads();

            const uint32_t aB = smem_u32(&sA[buf][0]);
            const uint32_t bB = smem_u32(&sB[buf][0]);
#pragma unroll
            for (int ks = 0; ks < 2; ks++) {       // two K=16 steps per BK=32
                uint32_t afr[2][4], bfr[4][4];
#pragma unroll
                for (int am = 0; am < 2; am++) {
                    uint32_t addr = aB +
                        ((wm * 32 + am * 16 + rsel) * SPAD + ks * 16 + ksel) * 2;
                    LDSM_X4(afr[am][0], afr[am][1], afr[am][2], afr[am][3], addr);
                }
#pragma unroll
                for (int bn = 0; bn < 4; bn++) {
                    uint32_t addr = bB +
                        ((wn * 64 + bn * 16 + rsel) * SPAD + ks * 16 + ksel) * 2;
                    LDSM_X4(bfr[bn][0], bfr[bn][1], bfr[bn][2], bfr[bn][3], addr);
                }
#pragma unroll
                for (int am = 0; am < 2; am++)
#pragma unroll
                    for (int j = 0; j < 8; j++) {
                        int bn = j >> 1, hi = j & 1;
                        MMA16816(acc[am][j], afr[am], bfr[bn][hi], bfr[bn][hi + 2]);
                    }
            }
            __syncthreads();
            buf ^= 1;
        }

        // ---- fused epilogue for this n-chunk ----
#pragma unroll
        for (int am = 0; am < 2; am++)
#pragma unroll
            for (int j = 0; j < 8; j++) {
                int nl = wn * 64 + j * 8 + q * 2;
                float wx = ws_s[nl], wy = ws_s[nl + 1];
                float vx = v_s[nl],  vy = v_s[nl + 1];
                rowacc[am * 2 + 0] += fast_tanh(acc[am][j][0] + wx) * vx
                                    + fast_tanh(acc[am][j][1] + wy) * vy;
                rowacc[am * 2 + 1] += fast_tanh(acc[am][j][2] + wx) * vx
                                    + fast_tanh(acc[am][j][3] + wy) * vy;
            }
    }

    // ---- cross-lane reduce over the 4-lane quad (different n, same rows) ----
#pragma unroll
    for (int k = 0; k < 4; k++) {
        rowacc[k] += __shfl_xor_sync(0xFFFFFFFF, rowacc[k], 1);
        rowacc[k] += __shfl_xor_sync(0xFFFFFFFF, rowacc[k], 2);
    }
    if (q == 0) {
        s_part[wn][wm * 32 + g]      = rowacc[0];
        s_part[wn][wm * 32 + g + 8]  = rowacc[1];
        s_part[wn][wm * 32 + g + 16] = rowacc[2];
        s_part[wn][wm * 32 + g + 24] = rowacc[3];
    }
    __syncthreads();
    if (tid < BM)
        g_scores[b * T_ + t0 + tid] = s_part[0][tid] + s_part[1][tid];
}

// ---------------------------------------------------------------------------
// Kernel 5: softmax over T per batch (raw exp, matching reference)
// ---------------------------------------------------------------------------
__global__ void softmax_kernel() {
    __shared__ float red[256];
    const int b = blockIdx.x;
    const int tid = threadIdx.x;
    float e[8];
    float s = 0.0f;
#pragma unroll
    for (int j = 0; j < 8; j++) {
        e[j] = __expf(g_scores[b * T_ + tid + j * 256]);
        s += e[j];
    }
    red[tid] = s;
    __syncthreads();
#pragma unroll
    for (int o = 128; o > 0; o >>= 1) {
        if (tid < o) red[tid] += red[tid + o];
        __syncthreads();
    }
    const float inv = 1.0f / red[0];
#pragma unroll
    for (int j = 0; j < 8; j++)
        g_probs[b * T_ + tid + j * 256] = e[j] * inv;
}

// ---------------------------------------------------------------------------
// Kernel 6: context partial sums  partial[b][tc][d] = sum_{t in chunk} a_t*h[t][d]
// ---------------------------------------------------------------------------
__global__ void ctx_partial_kernel(const float* __restrict__ h) {
    __shared__ float ap[256];
    const int tc = blockIdx.x;   // 8 chunks of 256
    const int b  = blockIdx.y;
    const int tid = threadIdx.x;
    ap[tid] = g_probs[b * T_ + tc * 256 + tid];
    __syncthreads();
    const float4* hp = (const float4*)h + ((size_t)b * T_ + tc * 256) * (D_ / 4) + tid;
    float4 acc = make_float4(0.f, 0.f, 0.f, 0.f);
#pragma unroll 4
    for (int r = 0; r < 256; r++) {
        float a = ap[r];
        float4 v = __ldg(hp + (size_t)r * (D_ / 4));
        acc.x = fmaf(a, v.x, acc.x);
        acc.y = fmaf(a, v.y, acc.y);
        acc.z = fmaf(a, v.z, acc.z);
        acc.w = fmaf(a, v.w, acc.w);
    }
    ((float4*)g_partial)[((size_t)b * 8 + tc) * (D_ / 4) + tid] = acc;
}

// ---------------------------------------------------------------------------
// Kernel 7: reduce partials -> output c[b][d]
// ---------------------------------------------------------------------------
__global__ void ctx_reduce_kernel(float* __restrict__ out) {
    const int b = blockIdx.x;
    const int tid = threadIdx.x;
    float4 s = make_float4(0.f, 0.f, 0.f, 0.f);
#pragma unroll
    for (int tc = 0; tc < 8; tc++) {
        float4 v = ((const float4*)g_partial)[((size_t)b * 8 + tc) * (D_ / 4) + tid];
        s.x += v.x; s.y += v.y; s.z += v.z; s.w += v.w;
    }
    ((float4*)out)[(size_t)b * (D_ / 4) + tid] = s;
}

// ---------------------------------------------------------------------------
// Launch
// ---------------------------------------------------------------------------
extern "C" void kernel_launch(void* const* d_in, const int* in_sizes, int n_in,
                              void* d_out, int out_size) {
    const float* s   = (const float*)d_in[0];   // [B, D]
    const float* h   = (const float*)d_in[1];   // [B, T, D]
    const float* W_a = (const float*)d_in[2];   // [D, A]
    const float* U_a = (const float*)d_in[3];   // [D, A]
    const float* v_a = (const float*)d_in[4];   // [A]
    float* out = (float*)d_out;                 // [B, D]

    convert_h_kernel<<<(M_ROWS * D_) / 4 / 256, 256>>>(h);
    transpose_U_kernel<<<dim3(32, 32), dim3(32, 8)>>>(U_a);
    ws_kernel<<<dim3(8, B_), 128>>>(s, W_a);
    scores_kernel<<<M_ROWS / BM, 256>>>(v_a);
    softmax_kernel<<<B_, 256>>>();
    ctx_partial_kernel<<<dim3(8, B_), 256>>>(h);
    ctx_reduce_kernel<<<B_, 256>>>(out);
}

// round 4
// speedup vs baseline: 1.0818x; 1.0818x over previous
#include <cuda_runtime.h>
#include <cuda_fp16.h>
#include <cstdint>

// ---------------------------------------------------------------------------
// Problem constants
// ---------------------------------------------------------------------------
#define B_   32
#define T_   2048
#define D_   1024
#define A_   1024
#define M_ROWS (B_ * T_)          // 65536

// scores GEMM tiling (HMMA mma.sync path — tcgen05 PTX not allowed at compute_103)
#define BM 128
#define BN 128
#define BK 32
#define N_CHUNKS (A_ / BN)        // 8
#define K_TILES  (D_ / BK)        // 32
#define SPAD 40                   // smem row stride in halves (80B)
#define STAGES 3
#define A_BYTES (BM * SPAD * 2)               // 10240
#define STAGE_BYTES (A_BYTES + BN * SPAD * 2) // 20480
#define DYN_SMEM (STAGES * STAGE_BYTES)       // 61440

// ---------------------------------------------------------------------------
// Device scratch (static __device__ arrays: the sanctioned no-alloc path)
// ---------------------------------------------------------------------------
__device__ __align__(16) __half g_h16[(size_t)M_ROWS * D_];   // 128 MB
__device__ __align__(16) __half g_U16t[(size_t)A_ * D_];      // U transposed: [a][d]
__device__ __align__(16) float  g_Ws[B_ * A_];
__device__ __align__(16) float  g_scores[B_ * T_];
__device__ __align__(16) float  g_probs[B_ * T_];
__device__ __align__(16) float  g_partial[B_ * 8 * D_];

// ---------------------------------------------------------------------------
// PTX helpers (portable: sm_80-era instructions only)
// ---------------------------------------------------------------------------
__device__ __forceinline__ uint32_t smem_u32(const void* p) {
    uint32_t a;
    asm("{ .reg .u64 t; cvta.to.shared.u64 t, %1; cvt.u32.u64 %0, t; }"
        : "=r"(a) : "l"(p));
    return a;
}

#define CP_ASYNC16(dst, src) \
    asm volatile("cp.async.cg.shared.global [%0], [%1], 16;" :: "r"(dst), "l"(src))
#define CP_COMMIT() asm volatile("cp.async.commit_group;" ::: "memory")
#define CP_WAIT1()  asm volatile("cp.async.wait_group 1;" ::: "memory")
#define CP_WAIT0()  asm volatile("cp.async.wait_group 0;" ::: "memory")

#define LDSM_X4(r0, r1, r2, r3, addr)                                          \
    asm volatile("ldmatrix.sync.aligned.m8n8.x4.shared.b16 {%0,%1,%2,%3}, [%4];" \
                 : "=r"(r0), "=r"(r1), "=r"(r2), "=r"(r3) : "r"(addr))

#define MMA16816(d, a, b0, b1)                                                 \
    asm volatile("mma.sync.aligned.m16n8k16.row.col.f32.f16.f16.f32 "          \
                 "{%0,%1,%2,%3}, {%4,%5,%6,%7}, {%8,%9}, {%0,%1,%2,%3};"       \
                 : "+f"((d)[0]), "+f"((d)[1]), "+f"((d)[2]), "+f"((d)[3])      \
                 : "r"((a)[0]), "r"((a)[1]), "r"((a)[2]), "r"((a)[3]),         \
                   "r"(b0), "r"(b1))

__device__ __forceinline__ float fast_tanh(float x) {
    x = fminf(15.0f, fmaxf(-15.0f, x));
    float e = __expf(2.0f * x);
    return __fdividef(e - 1.0f, e + 1.0f);
}

// ---------------------------------------------------------------------------
// Kernel 1: convert h fp32 -> fp16 (one float4 per thread)
// ---------------------------------------------------------------------------
__global__ void convert_h_kernel(const float* __restrict__ h) {
    size_t i = (size_t)blockIdx.x * 256 + threadIdx.x;   // float4 index
    float4 v = __ldg(((const float4*)h) + i);
    __half2 lo = __floats2half2_rn(v.x, v.y);
    __half2 hi = __floats2half2_rn(v.z, v.w);
    uint2 out;
    out.x = *(uint32_t*)&lo;
    out.y = *(uint32_t*)&hi;
    ((uint2*)g_h16)[i] = out;
}

// ---------------------------------------------------------------------------
// Kernel 2: transpose + convert U_a [d][a] fp32 -> g_U16t [a][d] fp16
// ---------------------------------------------------------------------------
__global__ void transpose_U_kernel(const float* __restrict__ U) {
    __shared__ float tile[32][33];
    int bx = blockIdx.x;  // a tile
    int by = blockIdx.y;  // d tile
    int tx = threadIdx.x, ty = threadIdx.y;
#pragma unroll
    for (int j = 0; j < 4; j++)
        tile[ty + j * 8][tx] = __ldg(&U[(size_t)(by * 32 + ty + j * 8) * A_ + bx * 32 + tx]);
    __syncthreads();
#pragma unroll
    for (int j = 0; j < 4; j++)
        g_U16t[(size_t)(bx * 32 + ty + j * 8) * D_ + by * 32 + tx] =
            __float2half_rn(tile[tx][ty + j * 8]);
}

// ---------------------------------------------------------------------------
// Kernel 3: Ws[b][a] = sum_d s[b][d] * W_a[d][a]   (fp32, small)
// ---------------------------------------------------------------------------
__global__ void ws_kernel(const float* __restrict__ s, const float* __restrict__ W) {
    __shared__ float ss[D_];
    int b = blockIdx.y;
    int a = blockIdx.x * 128 + threadIdx.x;
    for (int i = threadIdx.x; i < D_; i += 128)
        ss[i] = __ldg(&s[b * D_ + i]);
    __syncthreads();
    float acc = 0.0f;
#pragma unroll 8
    for (int d = 0; d < D_; d++)
        acc = fmaf(ss[d], __ldg(&W[(size_t)d * A_ + a]), acc);
    g_Ws[b * A_ + a] = acc;
}

// ---------------------------------------------------------------------------
// Kernel 4: fused scores GEMM (HMMA) + tanh + v_a reduction
//   scores[b,t] = sum_a tanh(Ws[b,a] + sum_d h[b,t,d]*U[d,a]) * v_a[a]
// 3-stage cp.async pipeline, 1 barrier per K-tile, incremental addressing.
// ---------------------------------------------------------------------------
__global__ void __launch_bounds__(256, 2)
scores_kernel(const float* __restrict__ v_a) {
    extern __shared__ char dsm[];
    __shared__ float ws_s[BN];
    __shared__ float v_s[BN];
    __shared__ float s_part[2][BM];

    const uint32_t base = smem_u32(dsm);
    const uint32_t stage_base[STAGES] = {base, base + STAGE_BYTES, base + 2 * STAGE_BYTES};

    const int tid = threadIdx.x;
    const int wid = tid >> 5;
    const int lane = tid & 31;
    const int wm = wid & 3;      // 4 warps over M
    const int wn = wid >> 2;     // 2 warps over N
    const int g = lane >> 2;
    const int q = lane & 3;

    const int row0 = blockIdx.x * BM;
    const int b = row0 >> 11;            // T_ = 2048
    const int t0 = row0 & (T_ - 1);

    // ldmatrix lane-invariant offsets (bytes within a stage)
    const int rsel = lane & 15;
    const int ksel = (lane >> 4) << 3;
    uint32_t aoff[2], boff[4];
#pragma unroll
    for (int am = 0; am < 2; am++)
        aoff[am] = ((wm * 32 + am * 16 + rsel) * SPAD + ksel) * 2;
#pragma unroll
    for (int bn = 0; bn < 4; bn++)
        boff[bn] = A_BYTES + ((wn * 64 + bn * 16 + rsel) * SPAD + ksel) * 2;

    // cp.async per-thread geometry (fixed across the whole kernel)
    int r_[4], c_[4], isB_[4];
    uint32_t dstoff[4];
#pragma unroll
    for (int i = 0; i < 4; i++) {
        int idx = tid + i * 256;          // 0..1023
        isB_[i] = idx >> 9;               // 0: A(h), 1: B(U)
        r_[i] = (idx & 511) >> 2;
        c_[i] = idx & 3;
        dstoff[i] = isB_[i] * A_BYTES + (r_[i] * SPAD + c_[i] * 8) * 2;
    }

    const __half* hbase = g_h16 + (size_t)row0 * D_;

    float rowacc[4] = {0.f, 0.f, 0.f, 0.f};

    for (int nc = 0; nc < N_CHUNKS; nc++) {
        const int n0 = nc * BN;
        __syncthreads();               // prior epilogue/compute done before restaging
        if (tid < BN) {
            ws_s[tid] = g_Ws[b * A_ + n0 + tid];
            v_s[tid]  = __ldg(&v_a[n0 + tid]);
        }

        float acc[2][8][4];
#pragma unroll
        for (int am = 0; am < 2; am++)
#pragma unroll
            for (int j = 0; j < 8; j++)
#pragma unroll
                for (int c = 0; c < 4; c++) acc[am][j][c] = 0.f;

        const __half* ubase = g_U16t + (size_t)n0 * D_;

        // per-thread running source pointers for this n-chunk
        const __half* cur[4];
#pragma unroll
        for (int i = 0; i < 4; i++)
            cur[i] = (isB_[i] ? ubase : hbase) + (size_t)r_[i] * D_ + c_[i] * 8;

        // ---- prologue: stage kt=0 and kt=1 ----
#pragma unroll
        for (int pf = 0; pf < 2; pf++) {
#pragma unroll
            for (int i = 0; i < 4; i++) {
                CP_ASYNC16(stage_base[pf] + dstoff[i], cur[i]);
                cur[i] += BK;
            }
            CP_COMMIT();
        }

        for (int kt = 0; kt < K_TILES; kt++) {
            if (kt < K_TILES - 1) { CP_WAIT1(); } else { CP_WAIT0(); }
            __syncthreads();           // stage kt resident; stage kt-1 free

            if (kt + 2 < K_TILES) {    // prefetch kt+2 into freed stage
                const uint32_t pb = stage_base[(kt + 2) % STAGES];
#pragma unroll
                for (int i = 0; i < 4; i++) {
                    CP_ASYNC16(pb + dstoff[i], cur[i]);
                    cur[i] += BK;
                }
                CP_COMMIT();
            }

            const uint32_t sb = stage_base[kt % STAGES];
#pragma unroll
            for (int ks = 0; ks < 2; ks++) {       // two K=16 steps per BK=32
                const uint32_t ko = ks * 32;       // 16 halves
                uint32_t afr[2][4], bfr[4][4];
#pragma unroll
                for (int am = 0; am < 2; am++)
                    LDSM_X4(afr[am][0], afr[am][1], afr[am][2], afr[am][3],
                            sb + aoff[am] + ko);
#pragma unroll
                for (int bn = 0; bn < 4; bn++)
                    LDSM_X4(bfr[bn][0], bfr[bn][1], bfr[bn][2], bfr[bn][3],
                            sb + boff[bn] + ko);
#pragma unroll
                for (int am = 0; am < 2; am++)
#pragma unroll
                    for (int j = 0; j < 8; j++) {
                        int bn = j >> 1, hi = j & 1;
                        MMA16816(acc[am][j], afr[am], bfr[bn][hi], bfr[bn][hi + 2]);
                    }
            }
        }

        // ---- fused epilogue for this n-chunk ----
#pragma unroll
        for (int am = 0; am < 2; am++)
#pragma unroll
            for (int j = 0; j < 8; j++) {
                int nl = wn * 64 + j * 8 + q * 2;
                float wx = ws_s[nl], wy = ws_s[nl + 1];
                float vx = v_s[nl],  vy = v_s[nl + 1];
                rowacc[am * 2 + 0] += fast_tanh(acc[am][j][0] + wx) * vx
                                    + fast_tanh(acc[am][j][1] + wy) * vy;
                rowacc[am * 2 + 1] += fast_tanh(acc[am][j][2] + wx) * vx
                                    + fast_tanh(acc[am][j][3] + wy) * vy;
            }
    }

    // ---- cross-lane reduce over the 4-lane quad (different n, same rows) ----
#pragma unroll
    for (int k = 0; k < 4; k++) {
        rowacc[k] += __shfl_xor_sync(0xFFFFFFFF, rowacc[k], 1);
        rowacc[k] += __shfl_xor_sync(0xFFFFFFFF, rowacc[k], 2);
    }
    if (q == 0) {
        s_part[wn][wm * 32 + g]      = rowacc[0];
        s_part[wn][wm * 32 + g + 8]  = rowacc[1];
        s_part[wn][wm * 32 + g + 16] = rowacc[2];
        s_part[wn][wm * 32 + g + 24] = rowacc[3];
    }
    __syncthreads();
    if (tid < BM)
        g_scores[b * T_ + t0 + tid] = s_part[0][tid] + s_part[1][tid];
}

// ---------------------------------------------------------------------------
// Kernel 5: softmax over T per batch (raw exp, matching reference)
// ---------------------------------------------------------------------------
__global__ void softmax_kernel() {
    __shared__ float red[256];
    const int b = blockIdx.x;
    const int tid = threadIdx.x;
    float e[8];
    float s = 0.0f;
#pragma unroll
    for (int j = 0; j < 8; j++) {
        e[j] = __expf(g_scores[b * T_ + tid + j * 256]);
        s += e[j];
    }
    red[tid] = s;
    __syncthreads();
#pragma unroll
    for (int o = 128; o > 0; o >>= 1) {
        if (tid < o) red[tid] += red[tid + o];
        __syncthreads();
    }
    const float inv = 1.0f / red[0];
#pragma unroll
    for (int j = 0; j < 8; j++)
        g_probs[b * T_ + tid + j * 256] = e[j] * inv;
}

// ---------------------------------------------------------------------------
// Kernel 6: context partial sums, reading fp16 h (half the bytes)
//   partial[b][tc][d] = sum_{t in chunk} a_t * h[t][d]
// ---------------------------------------------------------------------------
__global__ void ctx_partial_kernel() {
    __shared__ float ap[256];
    const int tc = blockIdx.x;   // 8 chunks of 256
    const int b  = blockIdx.y;
    const int tid = threadIdx.x;
    ap[tid] = g_probs[b * T_ + tc * 256 + tid];
    __syncthreads();
    // each thread owns 4 consecutive d (one uint2 = 4 halves)
    const uint2* hp = (const uint2*)(g_h16 + ((size_t)b * T_ + tc * 256) * D_) + tid;
    float4 acc = make_float4(0.f, 0.f, 0.f, 0.f);
#pragma unroll 4
    for (int r = 0; r < 256; r++) {
        float a = ap[r];
        uint2 v = __ldg(hp + (size_t)r * (D_ / 4));
        float2 f0 = __half22float2(*(const __half2*)&v.x);
        float2 f1 = __half22float2(*(const __half2*)&v.y);
        acc.x = fmaf(a, f0.x, acc.x);
        acc.y = fmaf(a, f0.y, acc.y);
        acc.z = fmaf(a, f1.x, acc.z);
        acc.w = fmaf(a, f1.y, acc.w);
    }
    ((float4*)g_partial)[((size_t)b * 8 + tc) * (D_ / 4) + tid] = acc;
}

// ---------------------------------------------------------------------------
// Kernel 7: reduce partials -> output c[b][d]
// ---------------------------------------------------------------------------
__global__ void ctx_reduce_kernel(float* __restrict__ out) {
    const int b = blockIdx.x;
    const int tid = threadIdx.x;
    float4 s = make_float4(0.f, 0.f, 0.f, 0.f);
#pragma unroll
    for (int tc = 0; tc < 8; tc++) {
        float4 v = ((const float4*)g_partial)[((size_t)b * 8 + tc) * (D_ / 4) + tid];
        s.x += v.x; s.y += v.y; s.z += v.z; s.w += v.w;
    }
    ((float4*)out)[(size_t)b * (D_ / 4) + tid] = s;
}

// ---------------------------------------------------------------------------
// Launch
// ---------------------------------------------------------------------------
extern "C" void kernel_launch(void* const* d_in, const int* in_sizes, int n_in,
                              void* d_out, int out_size) {
    const float* s   = (const float*)d_in[0];   // [B, D]
    const float* h   = (const float*)d_in[1];   // [B, T, D]
    const float* W_a = (const float*)d_in[2];   // [D, A]
    const float* U_a = (const float*)d_in[3];   // [D, A]
    const float* v_a = (const float*)d_in[4];   // [A]
    float* out = (float*)d_out;                 // [B, D]

    cudaFuncSetAttribute(scores_kernel,
                         cudaFuncAttributeMaxDynamicSharedMemorySize, DYN_SMEM);

    convert_h_kernel<<<(M_ROWS * D_) / 4 / 256, 256>>>(h);
    transpose_U_kernel<<<dim3(32, 32), dim3(32, 8)>>>(U_a);
    ws_kernel<<<dim3(8, B_), 128>>>(s, W_a);
    scores_kernel<<<M_ROWS / BM, 256, DYN_SMEM>>>(v_a);
    softmax_kernel<<<B_, 256>>>();
    ctx_partial_kernel<<<dim3(8, B_), 256>>>();
    ctx_reduce_kernel<<<B_, 256>>>(out);
}